// round 15
// baseline (speedup 1.0000x reference)
#include <cuda_runtime.h>
#include <cuda_fp16.h>
#include <stdint.h>

#define NN 100000
#define EE 1600000
#define GG 128
#define SLOT 64   // payload slots per destination (Poisson(16) max << 64)
#define NBG 782   // gemm blocks (128 rows each)
#define NBS 6250  // scatter blocks (256 edges each)
#define NBF (NBG * 9)  // 7038 >= NBG+NBS = 7032; we launch 7032

// ---------------- scratch (static device globals; no allocation) ----------------
__device__ __align__(16) float g_dinv[NN];
__device__ __align__(16) int   g_cursor[NN];
__device__ __align__(16) int2  g_pay[(size_t)NN * SLOT];   // {src, w-as-bits} binned by dest
__device__ __align__(16) __half g_bufA[(size_t)NN * 64];   // h*dinv (gemm output, fp16)
__device__ __align__(16) __half g_bufC[(size_t)NN * 64];   // ACTIVATED conv output layers 1-2 (fp16)
__device__ __align__(16) float g_pooled[GG * 64];
__device__ __align__(16) float g_bnsc[3][64];
__device__ __align__(16) float g_bnsh[3][64];

struct BNParams { const float* p[12]; };  // (gamma,beta,mean,var) x 3 layers

// ---------------- mma helpers ----------------
__device__ __forceinline__ unsigned s2u(const void* p) {
    unsigned a;
    asm("{ .reg .u64 t; cvta.to.shared.u64 t, %1; cvt.u32.u64 %0, t; }" : "=r"(a) : "l"(p));
    return a;
}
__device__ __forceinline__ void ldsm_x4(unsigned& r0, unsigned& r1, unsigned& r2, unsigned& r3,
                                        unsigned addr) {
    asm volatile("ldmatrix.sync.aligned.m8n8.x4.shared.b16 {%0,%1,%2,%3}, [%4];"
                 : "=r"(r0), "=r"(r1), "=r"(r2), "=r"(r3) : "r"(addr));
}
__device__ __forceinline__ void ldsm_x4t(unsigned& r0, unsigned& r1, unsigned& r2, unsigned& r3,
                                         unsigned addr) {
    asm volatile("ldmatrix.sync.aligned.m8n8.x4.trans.shared.b16 {%0,%1,%2,%3}, [%4];"
                 : "=r"(r0), "=r"(r1), "=r"(r2), "=r"(r3) : "r"(addr));
}
__device__ __forceinline__ void mma16816(float* c, unsigned a0, unsigned a1, unsigned a2,
                                         unsigned a3, unsigned b0, unsigned b1) {
    asm volatile(
        "mma.sync.aligned.m16n8k16.row.col.f32.f16.f16.f32 "
        "{%0,%1,%2,%3}, {%4,%5,%6,%7}, {%8,%9}, {%0,%1,%2,%3};"
        : "+f"(c[0]), "+f"(c[1]), "+f"(c[2]), "+f"(c[3])
        : "r"(a0), "r"(a1), "r"(a2), "r"(a3), "r"(b0), "r"(b1));
}

// ---------------- prep: zero cursor/pooled, BN consts ----------------
__global__ void k_prep(BNParams bp) {
    int i = blockIdx.x * blockDim.x + threadIdx.x;
    if (i < NN) g_cursor[i] = 0;
    if (i < GG * 64) g_pooled[i] = 0.0f;
    if (i < 3 * 64) {
        int l = i >> 6, f = i & 63;
        const float* ga = bp.p[l * 4 + 0];
        const float* be = bp.p[l * 4 + 1];
        const float* mn = bp.p[l * 4 + 2];
        const float* va = bp.p[l * 4 + 3];
        float sc = ga[f] * rsqrtf(va[f] + 1e-5f);
        g_bnsc[l][f] = sc;
        g_bnsh[l][f] = be[f] - mn[f] * sc;
    }
}

// ---------------- GEMM body (device): bufA = (in @ W) [* dinv[row] if SCALE]  (fp16) ------
// 256 threads / 8 warps; one 128-row x 64-col tile.
__device__ __forceinline__ void gemm_core(const float* in32, const float* W,
                                          int tile, int scale) {
    __shared__ __align__(16) __half sA[128 * 72];  // row r at r*72 (144B stride)
    __shared__ __align__(16) __half sW[64 * 72];
    int t = threadIdx.x;   // 256
    int r0 = tile * 128;

    const float4* W4 = (const float4*)W;
#pragma unroll
    for (int j = 0; j < 4; j++) {
        int idx = t + 256 * j;
        float4 v = W4[idx];
        int k = idx >> 4, c4 = idx & 15;
        __half2 h0 = __floats2half2_rn(v.x, v.y);
        __half2 h1 = __floats2half2_rn(v.z, v.w);
        *(uint2*)&sW[k * 72 + c4 * 4] = make_uint2(*(unsigned*)&h0, *(unsigned*)&h1);
    }

    if (in32 != 0) {
#pragma unroll
        for (int j = 0; j < 8; j++) {
            int idx = t + 256 * j;
            int rr = idx >> 4, c4 = idx & 15;
            int gr = r0 + rr;
            float4 v = make_float4(0.f, 0.f, 0.f, 0.f);
            if (gr < NN) v = *(const float4*)(in32 + (size_t)gr * 64 + c4 * 4);
            __half2 h0 = __floats2half2_rn(v.x, v.y);
            __half2 h1 = __floats2half2_rn(v.z, v.w);
            *(uint2*)&sA[rr * 72 + c4 * 4] = make_uint2(*(unsigned*)&h0, *(unsigned*)&h1);
        }
    } else {
        const __half* in = g_bufC;
#pragma unroll
        for (int j = 0; j < 4; j++) {
            int idx = t + 256 * j;
            int rr = idx >> 3, c8 = (idx & 7) * 8;
            int gr = r0 + rr;
            uint4 v = make_uint4(0, 0, 0, 0);
            if (gr < NN) v = *(const uint4*)(in + (size_t)gr * 64 + c8);
            *(uint4*)&sA[rr * 72 + c8] = v;
        }
    }
    __syncthreads();

    int warp = t >> 5, lane = t & 31;
    int mrow = warp * 16;
    unsigned aBase = s2u(sA), wBase = s2u(sW);
    int sub = lane >> 3, lr = lane & 7;

    float acc[8][4];
#pragma unroll
    for (int j = 0; j < 8; j++)
#pragma unroll
        for (int i = 0; i < 4; i++) acc[j][i] = 0.f;

#pragma unroll
    for (int kk = 0; kk < 4; kk++) {
        int arow = mrow + (sub & 1) * 8 + lr;
        int acol = kk * 16 + (sub >> 1) * 8;
        unsigned a0, a1, a2, a3;
        ldsm_x4(a0, a1, a2, a3, aBase + (unsigned)(arow * 72 + acol) * 2);
#pragma unroll
        for (int jj = 0; jj < 4; jj++) {
            int brow = kk * 16 + (sub & 1) * 8 + lr;
            int bcol = (jj * 2 + (sub >> 1)) * 8;
            unsigned b0, b1, b2, b3;
            ldsm_x4t(b0, b1, b2, b3, wBase + (unsigned)(brow * 72 + bcol) * 2);
            mma16816(acc[jj * 2],     a0, a1, a2, a3, b0, b1);
            mma16816(acc[jj * 2 + 1], a0, a1, a2, a3, b2, b3);
        }
    }

    int g1 = r0 + mrow + (lane >> 2);
    int g2 = g1 + 8;
    int cq = (lane & 3) * 2;
    float dv1 = 1.f, dv2 = 1.f;
    if (scale) {
        dv1 = (g1 < NN) ? g_dinv[g1] : 0.f;
        dv2 = (g2 < NN) ? g_dinv[g2] : 0.f;
    }
#pragma unroll
    for (int j = 0; j < 8; j++) {
        if (g1 < NN) {
            __half2 h = __floats2half2_rn(acc[j][0] * dv1, acc[j][1] * dv1);
            *(__half2*)&g_bufA[(size_t)g1 * 64 + j * 8 + cq] = h;
        }
        if (g2 < NN) {
            __half2 h = __floats2half2_rn(acc[j][2] * dv2, acc[j][3] * dv2);
            *(__half2*)&g_bufA[(size_t)g2 * 64 + j * 8 + cq] = h;
        }
    }
}

// ---------------- fat kernel: scatter blocks interleaved with gemm1 (unscaled) blocks ------
// every 9th block (b%9==0, b/9<NBG) is a gemm tile; others are scatter chunks.
__global__ void __launch_bounds__(256) k_fat(const float* __restrict__ x,
                                             const float* __restrict__ W1,
                                             const int* __restrict__ row,
                                             const int* __restrict__ col,
                                             const float* __restrict__ w) {
    int b = blockIdx.x;
    int g = b / 9;
    if ((b % 9) == 0 && g < NBG) {
        gemm_core(x, W1, g, 0);      // unscaled h -> bufA
        return;
    }
    int nGemmBefore = (b + 8) / 9;
    if (nGemmBefore > NBG) nGemmBefore = NBG;
    int sidx = b - nGemmBefore;      // 0..NBS-1, each exactly once
    int e = sidx * 256 + threadIdx.x;
    if (e >= EE) return;
    int r = row[e];
    int c = col[e];
    int pos = atomicAdd(&g_cursor[c], 1);
    if (pos > SLOT - 1) pos = SLOT - 1;   // unreachable; memory safety only
    g_pay[(size_t)c * SLOT + pos] = make_int2(r, __float_as_int(w[e]));
}

// ---------------- finscale: dinv from bins, then scale bufA row in place ----------------
// warp per destination: lanes 0-15 sum w; all lanes scale the 128B row.
__global__ void __launch_bounds__(256) k_finscale() {
    int warp = threadIdx.x >> 5;
    int lane = threadIdx.x & 31;
    int c = blockIdx.x * 8 + warp;        // NN % 8 == 0
    int cnt = g_cursor[c];
    if (cnt > SLOT) cnt = SLOT;
    const int2* __restrict__ pay = g_pay + (size_t)c * SLOT;

    float s = 0.f;
    for (int e = lane; e < cnt; e += 32) s += __int_as_float(__ldg(&pay[e]).y);
#pragma unroll
    for (int off = 16; off > 0; off >>= 1)
        s += __shfl_xor_sync(0xFFFFFFFFu, s, off);
    float dv = rsqrtf(1.0f + s);
    if (lane == 0) g_dinv[c] = dv;

    __half2* rowp = (__half2*)(g_bufA + (size_t)c * 64);
    __half2 v = rowp[lane];
    float2 f = __half22float2(v);
    rowp[lane] = __floats2half2_rn(f.x * dv, f.y * dv);
}

// ---------------- binned aggregation (warp per destination) -> activated fp16 bufC ----------
__global__ void __launch_bounds__(256) k_agg(const float* __restrict__ bias, int l) {
    int warp = threadIdx.x >> 5;
    int lane = threadIdx.x & 31;
    int c = blockIdx.x * 8 + warp;          // NN % 8 == 0
    int half = lane >> 4;
    int q = lane & 15;
    int cnt = g_cursor[c];
    if (cnt > SLOT) cnt = SLOT;
    const int2* __restrict__ pay = g_pay + (size_t)c * SLOT;

    const uint2* __restrict__ A2 = (const uint2*)g_bufA;   // 16 uint2 per 64-feat row

    float4 acc = make_float4(0.f, 0.f, 0.f, 0.f);
    for (int e = half; e < cnt; e += 2) {
        int2 p = __ldg(&pay[e]);
        uint2 r = __ldg(&A2[(size_t)p.x * 16 + q]);
        float n = __int_as_float(p.y);
        float2 f0 = __half22float2(*(__half2*)&r.x);
        float2 f1 = __half22float2(*(__half2*)&r.y);
        acc.x += f0.x * n; acc.y += f0.y * n;
        acc.z += f1.x * n; acc.w += f1.y * n;
    }
    acc.x += __shfl_xor_sync(0xFFFFFFFFu, acc.x, 16);
    acc.y += __shfl_xor_sync(0xFFFFFFFFu, acc.y, 16);
    acc.z += __shfl_xor_sync(0xFFFFFFFFu, acc.z, 16);
    acc.w += __shfl_xor_sync(0xFFFFFFFFu, acc.w, 16);

    if (half == 0) {
        float dv = g_dinv[c];
        uint2 sr = __ldg(&A2[(size_t)c * 16 + q]);         // h[c]*dinv[c]
        float2 s0 = __half22float2(*(__half2*)&sr.x);
        float2 s1 = __half22float2(*(__half2*)&sr.y);
        float4 b = *(const float4*)(bias + q * 4);
        float4 sc = *(const float4*)&g_bnsc[l][q * 4];
        float4 sh = *(const float4*)&g_bnsh[l][q * 4];
        float o0 = fmaxf((acc.x + s0.x) * dv + b.x, 0.f) * sc.x + sh.x;
        float o1 = fmaxf((acc.y + s0.y) * dv + b.y, 0.f) * sc.y + sh.y;
        float o2 = fmaxf((acc.z + s1.x) * dv + b.z, 0.f) * sc.z + sh.z;
        float o3 = fmaxf((acc.w + s1.y) * dv + b.w, 0.f) * sc.w + sh.w;
        __half2 h0 = __floats2half2_rn(o0, o1);
        __half2 h1 = __floats2half2_rn(o2, o3);
        *(uint2*)&g_bufC[(size_t)c * 64 + q * 4] =
            make_uint2(*(unsigned*)&h0, *(unsigned*)&h1);
    }
}

// ---------------- layer-3 aggregation + BN3 + global_add_pool ----------------
__global__ void __launch_bounds__(256) k_agg3(const float* __restrict__ bias,
                                              const int* __restrict__ batch) {
    __shared__ float sacc[64];
    __shared__ int sbatch[8];
    int warp = threadIdx.x >> 5;
    int lane = threadIdx.x & 31;
    int c = blockIdx.x * 8 + warp;          // NN % 8 == 0
    int half = lane >> 4;
    int q = lane & 15;
    int cnt = g_cursor[c];
    if (cnt > SLOT) cnt = SLOT;
    const int2* __restrict__ pay = g_pay + (size_t)c * SLOT;
    const uint2* __restrict__ A2 = (const uint2*)g_bufA;

    if (threadIdx.x < 64) sacc[threadIdx.x] = 0.f;
    if (lane == 0) sbatch[warp] = batch[c];

    float4 acc = make_float4(0.f, 0.f, 0.f, 0.f);
    for (int e = half; e < cnt; e += 2) {
        int2 p = __ldg(&pay[e]);
        uint2 r = __ldg(&A2[(size_t)p.x * 16 + q]);
        float n = __int_as_float(p.y);
        float2 f0 = __half22float2(*(__half2*)&r.x);
        float2 f1 = __half22float2(*(__half2*)&r.y);
        acc.x += f0.x * n; acc.y += f0.y * n;
        acc.z += f1.x * n; acc.w += f1.y * n;
    }
    acc.x += __shfl_xor_sync(0xFFFFFFFFu, acc.x, 16);
    acc.y += __shfl_xor_sync(0xFFFFFFFFu, acc.y, 16);
    acc.z += __shfl_xor_sync(0xFFFFFFFFu, acc.z, 16);
    acc.w += __shfl_xor_sync(0xFFFFFFFFu, acc.w, 16);

    __syncthreads();
    bool uni = true;
#pragma unroll
    for (int i = 1; i < 8; i++) uni &= (sbatch[i] == sbatch[0]);

    if (half == 0) {
        float dv = g_dinv[c];
        uint2 sr = __ldg(&A2[(size_t)c * 16 + q]);
        float2 s0 = __half22float2(*(__half2*)&sr.x);
        float2 s1 = __half22float2(*(__half2*)&sr.y);
        float4 b = *(const float4*)(bias + q * 4);
        float4 sc = *(const float4*)&g_bnsc[2][q * 4];
        float4 sh = *(const float4*)&g_bnsh[2][q * 4];
        float o0 = ((acc.x + s0.x) * dv + b.x) * sc.x + sh.x;
        float o1 = ((acc.y + s0.y) * dv + b.y) * sc.y + sh.y;
        float o2 = ((acc.z + s1.x) * dv + b.z) * sc.z + sh.z;
        float o3 = ((acc.w + s1.y) * dv + b.w) * sc.w + sh.w;
        if (uni) {
            atomicAdd(&sacc[q * 4 + 0], o0);
            atomicAdd(&sacc[q * 4 + 1], o1);
            atomicAdd(&sacc[q * 4 + 2], o2);
            atomicAdd(&sacc[q * 4 + 3], o3);
        } else {
            int bg = sbatch[warp];
            atomicAdd(&g_pooled[bg * 64 + q * 4 + 0], o0);
            atomicAdd(&g_pooled[bg * 64 + q * 4 + 1], o1);
            atomicAdd(&g_pooled[bg * 64 + q * 4 + 2], o2);
            atomicAdd(&g_pooled[bg * 64 + q * 4 + 3], o3);
        }
    }
    __syncthreads();
    if (uni && threadIdx.x < 64)
        atomicAdd(&g_pooled[sbatch[0] * 64 + threadIdx.x], sacc[threadIdx.x]);
}

// ---------------- gemm kernels for layers 2-3 ----------------
__global__ void __launch_bounds__(256) k_gemm23(const float* __restrict__ W) {
    gemm_core(0, W, blockIdx.x, 1);
}

// ---------------- FC ----------------
__global__ void k_fc(const float* __restrict__ Wfc, const float* __restrict__ bfc,
                     float* __restrict__ out) {
    int g = threadIdx.x;  // 128
    float acc = 0.f;
#pragma unroll
    for (int k = 0; k < 64; k++)
        acc += fmaxf(g_pooled[g * 64 + k], 0.f) * Wfc[k];
    out[g] = acc + bfc[0];
}

// ---------------- launch ----------------
extern "C" void kernel_launch(void* const* d_in, const int* in_sizes, int n_in,
                              void* d_out, int out_size) {
    const float* x     = (const float*)d_in[0];
    const int*   ei    = (const int*)d_in[1];
    const int*   row   = ei;
    const int*   col   = ei + EE;
    const float* ew    = (const float*)d_in[2];
    const int*   batch = (const int*)d_in[3];
    const float* W1 = (const float*)d_in[4];
    const float* b1 = (const float*)d_in[5];
    const float* W2 = (const float*)d_in[6];
    const float* b2 = (const float*)d_in[7];
    const float* W3 = (const float*)d_in[8];
    const float* b3 = (const float*)d_in[9];
    const float* Wfc = (const float*)d_in[10];
    const float* bfc = (const float*)d_in[11];

    BNParams bp;
    for (int i = 0; i < 12; i++) bp.p[i] = (const float*)d_in[12 + i];

    int nb_n = (NN + 255) / 256;            // 391
    int nb_fat = NBG + NBS;                 // 7032
    int nb_agg = NN / 8;                    // 12500

    // prep, then overlapped scatter + gemm1
    k_prep<<<nb_n, 256>>>(bp);
    k_fat<<<nb_fat, 256>>>(x, W1, row, col, ew);
    k_finscale<<<nb_agg, 256>>>();

    // layer 1 agg
    k_agg<<<nb_agg, 256>>>(b1, 0);
    // layer 2
    k_gemm23<<<NBG, 256>>>(W2);
    k_agg<<<nb_agg, 256>>>(b2, 1);
    // layer 3 + fused BN3/pool
    k_gemm23<<<NBG, 256>>>(W3);
    k_agg3<<<nb_agg, 256>>>(b3, batch);

    // fc
    k_fc<<<1, 128>>>(Wfc, bfc, (float*)d_out);
}